// round 3
// baseline (speedup 1.0000x reference)
#include <cuda_runtime.h>
#include <cstdint>
#include <cstddef>

#define Bn   2
#define Ln   2048
#define Hn   768
#define DIn  1536
#define Nn   16
#define Rn   48
#define BLn  (Bn*Ln)     /* 4096 */
#define SP   (Rn + 2*Nn) /* 80 */

// -------- scratch (static device globals; no allocation allowed) --------
__device__ float g_proj [(size_t)BLn * 2 * DIn];  // in_proj output (h | gate)
__device__ float g_h    [(size_t)BLn * DIn];      // conv+silu output
__device__ float g_ssm  [(size_t)BLn * SP];       // x_proj output (dt_raw|B|C)
__device__ float g_dtraw[(size_t)BLn * Rn];       // tf32-rounded dt_raw copy
__device__ float g_dt   [(size_t)BLn * DIn];      // softplus(dt)
__device__ float g_y    [(size_t)BLn * DIn];      // scan output (tf32-rounded)
__device__ float g_xr   [(size_t)BLn * Hn];       // tf32-rounded x
__device__ float g_w1   [(size_t)Hn * 2 * DIn];   // tf32-rounded in_proj_w
__device__ float g_w2   [(size_t)Rn * DIn];       // tf32-rounded dt_proj_w
__device__ float g_w3   [(size_t)DIn * Hn];       // tf32-rounded out_proj_w

__device__ __forceinline__ float sigmoidf_(float x) { return 1.f / (1.f + __expf(-x)); }
__device__ __forceinline__ uint32_t f2tf(float f) {
    uint32_t u; asm("cvt.rna.tf32.f32 %0, %1;" : "=r"(u) : "f"(f)); return u;
}
__device__ __forceinline__ float roundtf(float f) { return __uint_as_float(f2tf(f)); }
__device__ __forceinline__ float softplusf_(float x) {
    return fmaxf(x, 0.f) + log1pf(__expf(-fabsf(x)));
}
__device__ __forceinline__ void cp16(void* s, const void* g) {
    uint32_t sa = (uint32_t)__cvta_generic_to_shared(s);
    asm volatile("cp.async.cg.shared.global [%0], [%1], 16;\n" :: "r"(sa), "l"(g));
}
__device__ __forceinline__ void cp_commit() {
    asm volatile("cp.async.commit_group;\n");
}
__device__ __forceinline__ void cp_wait0() {
    asm volatile("cp.async.wait_group 0;\n");
}

// ============================================================================
// Pre-round x + weights to tf32 (vectorized float4, grid-stride).
// ============================================================================
#define S0 ((size_t)BLn * Hn)        /* x      3,145,728 */
#define S1 ((size_t)Hn * 2 * DIn)    /* w1     2,359,296 */
#define S2 ((size_t)Rn * DIn)        /* w2        73,728 */
#define S3 ((size_t)DIn * Hn)        /* w3     1,179,648 */
__global__ __launch_bounds__(256)
void preround(const float* __restrict__ x,  const float* __restrict__ w1,
              const float* __restrict__ w2, const float* __restrict__ w3)
{
    size_t i4 = (size_t)blockIdx.x * blockDim.x + threadIdx.x;
    size_t i = i4 * 4;
    const float* src; float* dst; size_t off;
    if (i < S0)                { src = x;  dst = g_xr; off = i; }
    else if (i < S0 + S1)      { src = w1; dst = g_w1; off = i - S0; }
    else if (i < S0 + S1 + S2) { src = w2; dst = g_w2; off = i - S0 - S1; }
    else if (i < S0+S1+S2+S3)  { src = w3; dst = g_w3; off = i - S0 - S1 - S2; }
    else return;
    float4 v = *(const float4*)(src + off);
    v.x = roundtf(v.x); v.y = roundtf(v.y); v.z = roundtf(v.z); v.w = roundtf(v.w);
    *(float4*)(dst + off) = v;
}

// ============================================================================
// TF32 tensor-core GEMM, cp.async double-buffered, operands pre-rounded.
// C[M,N] = A[M,K](lda) @ B[K,N]. Tile 128x128x16, 8 warps (64x32 each).
// EPI==1: C = softplus(C + bias[n])
// ============================================================================
template<int EPI>
__global__ __launch_bounds__(256, 2)
void tgemm(const float* __restrict__ A, int lda,
           const float* __restrict__ Bm,
           float* __restrict__ C, int N, int K,
           const float* __restrict__ bias)
{
    // A [m][k] row stride 20 (conflict-free), B [k][n] row stride 136
    __shared__ float As[2][128][20];
    __shared__ float Bs[2][16][136];

    const int tid  = threadIdx.x;
    const int lane = tid & 31;
    const int warp = tid >> 5;
    const int wm   = warp >> 2;
    const int wn   = warp & 3;
    const int m0   = wm * 64;
    const int n0   = wn * 32;
    const int g    = lane >> 2;
    const int c    = lane & 3;

    const int bm = blockIdx.y << 7;
    const int bn = blockIdx.x << 7;

    const int ar = tid >> 2;            // 0..63
    const int ac = (tid & 3) << 2;      // 0,4,8,12
    const int br = tid >> 5;            // 0..7
    const int bc = (tid & 31) << 2;     // 0..124

    const float* Ap0 = A + (size_t)(bm + ar) * lda + ac;
    const float* Ap1 = Ap0 + (size_t)64 * lda;
    const float* Bp0 = Bm + (size_t)br * N + bn + bc;
    const float* Bp1 = Bp0 + (size_t)8 * N;

    float acc[4][4][4];
#pragma unroll
    for (int i = 0; i < 4; i++)
#pragma unroll
        for (int j = 0; j < 4; j++)
#pragma unroll
            for (int q = 0; q < 4; q++) acc[i][j][q] = 0.f;

    auto load_stage = [&](int kt, int s) {
        const int k0 = kt << 4;
        cp16(&As[s][ar][ac],      Ap0 + k0);
        cp16(&As[s][ar + 64][ac], Ap1 + k0);
        cp16(&Bs[s][br][bc],      Bp0 + (size_t)k0 * N);
        cp16(&Bs[s][br + 8][bc],  Bp1 + (size_t)k0 * N);
    };
    auto compute = [&](int buf) {
#pragma unroll
        for (int ks = 0; ks < 2; ks++) {
            const int kb = ks << 3;
            uint32_t af[4][4], bf[4][2];
#pragma unroll
            for (int i = 0; i < 4; i++) {
                const int r = m0 + i * 16 + g;
                af[i][0] = __float_as_uint(As[buf][r][kb + c]);
                af[i][1] = __float_as_uint(As[buf][r + 8][kb + c]);
                af[i][2] = __float_as_uint(As[buf][r][kb + c + 4]);
                af[i][3] = __float_as_uint(As[buf][r + 8][kb + c + 4]);
            }
#pragma unroll
            for (int j = 0; j < 4; j++) {
                const int col = n0 + j * 8 + g;
                bf[j][0] = __float_as_uint(Bs[buf][kb + c][col]);
                bf[j][1] = __float_as_uint(Bs[buf][kb + c + 4][col]);
            }
#pragma unroll
            for (int i = 0; i < 4; i++)
#pragma unroll
                for (int j = 0; j < 4; j++)
                    asm volatile(
                        "mma.sync.aligned.m16n8k8.row.col.f32.tf32.tf32.f32 "
                        "{%0,%1,%2,%3}, {%4,%5,%6,%7}, {%8,%9}, {%0,%1,%2,%3};\n"
                        : "+f"(acc[i][j][0]), "+f"(acc[i][j][1]),
                          "+f"(acc[i][j][2]), "+f"(acc[i][j][3])
                        : "r"(af[i][0]), "r"(af[i][1]), "r"(af[i][2]), "r"(af[i][3]),
                          "r"(bf[j][0]), "r"(bf[j][1]));
        }
    };

    const int nk = K >> 4;
    load_stage(0, 0);
    cp_commit();

    for (int kt = 0; kt < nk; ++kt) {
        cp_wait0();
        __syncthreads();
        if (kt + 1 < nk) load_stage(kt + 1, (kt + 1) & 1);
        cp_commit();
        compute(kt & 1);
    }

    // epilogue
#pragma unroll
    for (int i = 0; i < 4; i++) {
        const int r0 = bm + m0 + i * 16 + g;
#pragma unroll
        for (int j = 0; j < 4; j++) {
            const int col = bn + n0 + j * 8 + 2 * c;
            float v00 = acc[i][j][0], v01 = acc[i][j][1];
            float v10 = acc[i][j][2], v11 = acc[i][j][3];
            if (EPI == 1) {
                const float b0v = bias[col], b1v = bias[col + 1];
                v00 = softplusf_(v00 + b0v);
                v01 = softplusf_(v01 + b1v);
                v10 = softplusf_(v10 + b0v);
                v11 = softplusf_(v11 + b1v);
            }
            *(float2*)&C[(size_t)r0 * N + col]       = make_float2(v00, v01);
            *(float2*)&C[(size_t)(r0 + 8) * N + col] = make_float2(v10, v11);
        }
    }
}

// ============================================================================
// Depthwise causal conv (K=4) + bias + SiLU.
// ============================================================================
__global__ __launch_bounds__(256)
void conv_silu(const float* __restrict__ proj,
               const float* __restrict__ cw,
               const float* __restrict__ cb,
               float* __restrict__ h)
{
    int idx = blockIdx.x * blockDim.x + threadIdx.x;
    int d  = idx % DIn;
    int bt = idx / DIn;
    int t  = bt % Ln;

    float4 w = *(const float4*)(cw + d * 4);
    float acc = cb[d];
    const float* p = proj + (size_t)bt * (2 * DIn) + d;
    const int s = 2 * DIn;
    if (t >= 3) acc = fmaf(p[-3 * s], w.x, acc);
    if (t >= 2) acc = fmaf(p[-2 * s], w.y, acc);
    if (t >= 1) acc = fmaf(p[-1 * s], w.z, acc);
    acc = fmaf(p[0], w.w, acc);
    h[idx] = acc * sigmoidf_(acc);
}

// ============================================================================
// x_proj GEMM: ssm[4096,80] = h[4096,1536] @ W[1536,80]. BM=32, BK=16.
// Also writes tf32-rounded dt_raw (cols 0..47) to g_dtraw.
// ============================================================================
__global__ __launch_bounds__(256)
void gemm_xproj(const float* __restrict__ A,
                const float* __restrict__ W,
                float* __restrict__ C)
{
    __shared__ float As[2][16][32];
    __shared__ float Ws[2][16][SP];

    const int tid = threadIdx.x;
    const int bm  = blockIdx.x << 5;
    const int ar  = tid >> 3;
    const int ac  = (tid & 7) << 1;
    const int tx  = tid & 15;
    const int ty  = tid >> 4;

    float acc[2][5];
#pragma unroll
    for (int i = 0; i < 2; i++)
#pragma unroll
        for (int j = 0; j < 5; j++) acc[i][j] = 0.f;

    const float* Ap = A + (size_t)(bm + ar) * DIn + ac;
    const int nk = DIn / 16;

    {
        float2 a2 = *(const float2*)Ap;
        As[0][ac][ar]     = a2.x;
        As[0][ac + 1][ar] = a2.y;
#pragma unroll
        for (int j = 0; j < 5; j++) {
            int e = tid + (j << 8);
            int k = e / SP, n2 = e % SP;
            Ws[0][k][n2] = W[k * SP + n2];
        }
    }
    __syncthreads();

    for (int kt = 0; kt < nk; ++kt) {
        const int buf = kt & 1;
        const bool more = (kt + 1 < nk);
        float2 a2n;
        float  wn[5];
        if (more) {
            a2n = *(const float2*)(Ap + (kt + 1) * 16);
#pragma unroll
            for (int j = 0; j < 5; j++) {
                int e = tid + (j << 8);
                int k = e / SP, n2 = e % SP;
                wn[j] = W[((kt + 1) * 16 + k) * SP + n2];
            }
        }
#pragma unroll
        for (int k = 0; k < 16; k++) {
            float rA0 = As[buf][k][ty * 2];
            float rA1 = As[buf][k][ty * 2 + 1];
#pragma unroll
            for (int j = 0; j < 5; j++) {
                float w = Ws[buf][k][tx * 5 + j];
                acc[0][j] = fmaf(rA0, w, acc[0][j]);
                acc[1][j] = fmaf(rA1, w, acc[1][j]);
            }
        }
        if (more) {
            const int nb = buf ^ 1;
            As[nb][ac][ar]     = a2n.x;
            As[nb][ac + 1][ar] = a2n.y;
#pragma unroll
            for (int j = 0; j < 5; j++) {
                int e = tid + (j << 8);
                int k = e / SP, n2 = e % SP;
                Ws[nb][k][n2] = wn[j];
            }
        }
        __syncthreads();
    }

#pragma unroll
    for (int i = 0; i < 2; i++) {
        const int row = bm + ty * 2 + i;
#pragma unroll
        for (int j = 0; j < 5; j++) {
            const int col = tx * 5 + j;
            float v = acc[i][j];
            C[(size_t)row * SP + col] = v;
            if (col < Rn) g_dtraw[(size_t)row * Rn + col] = roundtf(v);
        }
    }
}

// ============================================================================
// Fused selective scan + skip + gating (writes tf32-rounded y).
// ============================================================================
__global__ __launch_bounds__(128)
void scan_kernel(const float* __restrict__ Alog, const float* __restrict__ Dp)
{
    __shared__ float s_h [2][32][8];
    __shared__ float s_dt[2][32][8];
    __shared__ float s_g [2][32][8];
    __shared__ float s_B [2][32][16];
    __shared__ float s_C [2][32][16];

    const int tid  = threadIdx.x;
    const int lane = tid & 31;
    const int w    = tid >> 5;
    const int n    = lane & 15;
    const int half = lane >> 4;
    const int dl   = (w << 1) + half;
    const int blk  = blockIdx.x;
    const int b    = blk / (DIn / 8);
    const int d0   = (blk % (DIn / 8)) << 3;
    const int d    = d0 + dl;
    const int bL   = b * Ln;

    const float A_dn = -__expf(Alog[d * Nn + n]);
    const float Dv   = Dp[d];
    float state = 0.f;

    float rh[2], rdt[2], rg[2], rB[4], rC[4];

    auto do_load = [&](int c) {
        int t0 = c << 5;
#pragma unroll
        for (int j = 0; j < 2; j++) {
            int e = tid + (j << 7);
            int t = e >> 3, dd = e & 7;
            int row = bL + t0 + t;
            rh[j]  = g_h [(size_t)row * DIn + d0 + dd];
            rdt[j] = g_dt[(size_t)row * DIn + d0 + dd];
            rg[j]  = g_proj[(size_t)row * (2 * DIn) + DIn + d0 + dd];
        }
#pragma unroll
        for (int j = 0; j < 4; j++) {
            int e = tid + (j << 7);
            int t = e >> 4, nn = e & 15;
            int row = bL + t0 + t;
            rB[j] = g_ssm[(size_t)row * SP + Rn + nn];
            rC[j] = g_ssm[(size_t)row * SP + Rn + Nn + nn];
        }
    };
    auto do_store = [&](int buf) {
#pragma unroll
        for (int j = 0; j < 2; j++) {
            int e = tid + (j << 7);
            int t = e >> 3, dd = e & 7;
            s_h [buf][t][dd] = rh[j];
            s_dt[buf][t][dd] = rdt[j];
            s_g [buf][t][dd] = rg[j];
        }
#pragma unroll
        for (int j = 0; j < 4; j++) {
            int e = tid + (j << 7);
            int t = e >> 4, nn = e & 15;
            s_B[buf][t][nn] = rB[j];
            s_C[buf][t][nn] = rC[j];
        }
    };

    do_load(0);
    do_store(0);
    __syncthreads();

    const int NC = Ln / 32;
    for (int c = 0; c < NC; c++) {
        const int buf = c & 1;
        if (c + 1 < NC) do_load(c + 1);
        const int t0 = c << 5;
#pragma unroll 8
        for (int t = 0; t < 32; t++) {
            float dtv = s_dt[buf][t][dl];
            float hv  = s_h [buf][t][dl];
            float Bv  = s_B [buf][t][n];
            float Cv  = s_C [buf][t][n];
            float dA  = __expf(A_dn * dtv);
            state = fmaf(dA, state, Bv * hv);
            float p = state * Cv;
            p += __shfl_xor_sync(0xffffffffu, p, 8);
            p += __shfl_xor_sync(0xffffffffu, p, 4);
            p += __shfl_xor_sync(0xffffffffu, p, 2);
            p += __shfl_xor_sync(0xffffffffu, p, 1);
            if (n == 0) {
                float gv = s_g[buf][t][dl];
                float yv = (p + hv * Dv) * gv * sigmoidf_(gv);
                g_y[(size_t)(bL + t0 + t) * DIn + d] = roundtf(yv);
            }
        }
        if (c + 1 < NC) do_store(buf ^ 1);
        __syncthreads();
    }
}

// ============================================================================
extern "C" void kernel_launch(void* const* d_in, const int* in_sizes, int n_in,
                              void* d_out, int out_size)
{
    const float* x          = (const float*)d_in[0];
    const float* in_proj_w  = (const float*)d_in[1];
    const float* conv_w     = (const float*)d_in[2];
    const float* conv_b     = (const float*)d_in[3];
    const float* x_proj_w   = (const float*)d_in[4];
    const float* dt_proj_w  = (const float*)d_in[5];
    const float* dt_proj_b  = (const float*)d_in[6];
    const float* out_proj_w = (const float*)d_in[7];
    const float* A_log      = (const float*)d_in[8];
    const float* D_param    = (const float*)d_in[9];
    float* out = (float*)d_out;

    float *proj, *h, *ssm, *dtraw, *dt, *y, *xr, *w1, *w2, *w3;
    cudaGetSymbolAddress((void**)&proj,  g_proj);
    cudaGetSymbolAddress((void**)&h,     g_h);
    cudaGetSymbolAddress((void**)&ssm,   g_ssm);
    cudaGetSymbolAddress((void**)&dtraw, g_dtraw);
    cudaGetSymbolAddress((void**)&dt,    g_dt);
    cudaGetSymbolAddress((void**)&y,     g_y);
    cudaGetSymbolAddress((void**)&xr,    g_xr);
    cudaGetSymbolAddress((void**)&w1,    g_w1);
    cudaGetSymbolAddress((void**)&w2,    g_w2);
    cudaGetSymbolAddress((void**)&w3,    g_w3);

    // 0) pre-round x + weights to tf32
    size_t tot4 = (S0 + S1 + S2 + S3) / 4;
    preround<<<(unsigned)((tot4 + 255) / 256), 256>>>(x, in_proj_w, dt_proj_w, out_proj_w);

    // 1) proj = x @ in_proj_w   [4096,3072], K=768
    tgemm<0><<<dim3((2 * DIn) / 128, BLn / 128), 256>>>(
        xr, Hn, w1, proj, 2 * DIn, Hn, nullptr);

    // 2) depthwise causal conv + SiLU -> g_h
    conv_silu<<<(BLn * DIn) / 256, 256>>>(proj, conv_w, conv_b, h);

    // 3) ssm = h @ x_proj_w   [4096,80], K=1536 (+ rounded dt_raw copy)
    gemm_xproj<<<BLn / 32, 256>>>(h, x_proj_w, ssm);

    // 4) dt = softplus(dt_raw @ dt_proj_w + b)   [4096,1536], K=48
    tgemm<1><<<dim3(DIn / 128, BLn / 128), 256>>>(
        dtraw, Rn, w2, dt, DIn, Rn, dt_proj_b);

    // 5) selective scan (+ skip + gating)
    scan_kernel<<<Bn * (DIn / 8), 128>>>(A_log, D_param);

    // 6) out = y @ out_proj_w   [4096,768], K=1536
    tgemm<0><<<dim3(Hn / 128, BLn / 128), 256>>>(
        y, DIn, w3, out, Hn, DIn, nullptr);
}

// round 4
// speedup vs baseline: 1.0432x; 1.0432x over previous
#include <cuda_runtime.h>
#include <cstdint>
#include <cstddef>

#define Bn   2
#define Ln   2048
#define Hn   768
#define DIn  1536
#define Nn   16
#define Rn   48
#define BLn  (Bn*Ln)     /* 4096 */
#define SP   (Rn + 2*Nn) /* 80 */

// -------- scratch (static device globals; no allocation allowed) --------
__device__ float g_proj [(size_t)BLn * 2 * DIn];  // in_proj output (h | gate)
__device__ float g_h    [(size_t)BLn * DIn];      // conv+silu output
__device__ float g_ssm  [(size_t)BLn * SP];       // x_proj output (dt_raw|B|C)
__device__ float g_dtraw[(size_t)BLn * Rn];       // tf32-rounded dt_raw copy
__device__ float g_dt   [(size_t)BLn * DIn];      // softplus(dt)
__device__ float g_y    [(size_t)BLn * DIn];      // scan output (tf32-rounded)
__device__ float g_xr   [(size_t)BLn * Hn];       // tf32-rounded x
__device__ float g_w1   [(size_t)Hn * 2 * DIn];   // tf32-rounded in_proj_w
__device__ float g_w2   [(size_t)Rn * DIn];       // tf32-rounded dt_proj_w
__device__ float g_w3   [(size_t)DIn * Hn];       // tf32-rounded out_proj_w

__device__ __forceinline__ float sigmoidf_(float x) { return 1.f / (1.f + __expf(-x)); }
__device__ __forceinline__ uint32_t f2tf(float f) {
    uint32_t u; asm("cvt.rna.tf32.f32 %0, %1;" : "=r"(u) : "f"(f)); return u;
}
__device__ __forceinline__ float roundtf(float f) { return __uint_as_float(f2tf(f)); }
__device__ __forceinline__ float softplusf_(float x) {
    return fmaxf(x, 0.f) + log1pf(__expf(-fabsf(x)));
}
__device__ __forceinline__ void cp16(void* s, const void* g) {
    uint32_t sa = (uint32_t)__cvta_generic_to_shared(s);
    asm volatile("cp.async.cg.shared.global [%0], [%1], 16;\n" :: "r"(sa), "l"(g));
}
__device__ __forceinline__ void cp_commit() {
    asm volatile("cp.async.commit_group;\n");
}
template<int NN>
__device__ __forceinline__ void cp_wait() {
    asm volatile("cp.async.wait_group %0;\n" :: "n"(NN));
}

// ============================================================================
// Pre-round x + weights to tf32 (vectorized float4).
// ============================================================================
#define S0 ((size_t)BLn * Hn)
#define S1 ((size_t)Hn * 2 * DIn)
#define S2 ((size_t)Rn * DIn)
#define S3 ((size_t)DIn * Hn)
__global__ __launch_bounds__(256)
void preround(const float* __restrict__ x,  const float* __restrict__ w1,
              const float* __restrict__ w2, const float* __restrict__ w3)
{
    size_t i4 = (size_t)blockIdx.x * blockDim.x + threadIdx.x;
    size_t i = i4 * 4;
    const float* src; float* dst; size_t off;
    if (i < S0)                { src = x;  dst = g_xr; off = i; }
    else if (i < S0 + S1)      { src = w1; dst = g_w1; off = i - S0; }
    else if (i < S0 + S1 + S2) { src = w2; dst = g_w2; off = i - S0 - S1; }
    else if (i < S0+S1+S2+S3)  { src = w3; dst = g_w3; off = i - S0 - S1 - S2; }
    else return;
    float4 v = *(const float4*)(src + off);
    v.x = roundtf(v.x); v.y = roundtf(v.y); v.z = roundtf(v.z); v.w = roundtf(v.w);
    *(float4*)(dst + off) = v;
}

__global__ __launch_bounds__(256)
void zero_ssm()
{
    size_t i = ((size_t)blockIdx.x * blockDim.x + threadIdx.x) * 4;
    if (i < (size_t)BLn * SP) *(float4*)&g_ssm[i] = make_float4(0.f, 0.f, 0.f, 0.f);
}

__global__ __launch_bounds__(256)
void round_dtraw()
{
    int i = blockIdx.x * blockDim.x + threadIdx.x;   // over BLn*Rn
    if (i >= BLn * Rn) return;
    int row = i / Rn, col = i - row * Rn;
    g_dtraw[i] = roundtf(g_ssm[(size_t)row * SP + col]);
}

// ============================================================================
// TF32 tensor-core GEMM, 4-stage cp.async pipeline, operands pre-rounded.
// C[M,N] = A[M,K](lda) @ B[K,N]. Tile 128x128x16, 8 warps (64x32 each).
// EPI==1: C = softplus(C + bias[n]).  Dynamic smem: 4*(128*20+16*136)*4 B.
// ============================================================================
#define TG_STAGES 4
#define TG_ASZ (128 * 20)
#define TG_BSZ (16 * 136)
#define TG_SMEM (TG_STAGES * (TG_ASZ + TG_BSZ) * 4)

template<int EPI>
__global__ __launch_bounds__(256, 2)
void tgemm(const float* __restrict__ A, int lda,
           const float* __restrict__ Bm,
           float* __restrict__ C, int N, int K,
           const float* __restrict__ bias)
{
    extern __shared__ float smem[];
    // stage s: A at smem + s*(ASZ+BSZ), B after it
    const int tid  = threadIdx.x;
    const int lane = tid & 31;
    const int warp = tid >> 5;
    const int wm   = warp >> 2;
    const int wn   = warp & 3;
    const int m0   = wm * 64;
    const int n0   = wn * 32;
    const int g    = lane >> 2;
    const int c    = lane & 3;

    const int bm = blockIdx.y << 7;
    const int bn = blockIdx.x << 7;

    const int ar = tid >> 2;            // 0..63
    const int ac = (tid & 3) << 2;      // 0,4,8,12
    const int br = tid >> 5;            // 0..7
    const int bc = (tid & 31) << 2;     // 0..124

    const float* Ap0 = A + (size_t)(bm + ar) * lda + ac;
    const float* Ap1 = Ap0 + (size_t)64 * lda;
    const float* Bp0 = Bm + (size_t)br * N + bn + bc;
    const float* Bp1 = Bp0 + (size_t)8 * N;

    float acc[4][4][4];
#pragma unroll
    for (int i = 0; i < 4; i++)
#pragma unroll
        for (int j = 0; j < 4; j++)
#pragma unroll
            for (int q = 0; q < 4; q++) acc[i][j][q] = 0.f;

    const int nk = K >> 4;

    auto load_stage = [&](int kt, int s) {
        float* As = smem + s * (TG_ASZ + TG_BSZ);
        float* Bs = As + TG_ASZ;
        const int k0 = kt << 4;
        cp16(&As[ar * 20 + ac],        Ap0 + k0);
        cp16(&As[(ar + 64) * 20 + ac], Ap1 + k0);
        cp16(&Bs[br * 136 + bc],       Bp0 + (size_t)k0 * N);
        cp16(&Bs[(br + 8) * 136 + bc], Bp1 + (size_t)k0 * N);
    };
    auto compute = [&](int s) {
        const float* As = smem + s * (TG_ASZ + TG_BSZ);
        const float* Bs = As + TG_ASZ;
#pragma unroll
        for (int ks = 0; ks < 2; ks++) {
            const int kb = ks << 3;
            uint32_t af[4][4], bf[4][2];
#pragma unroll
            for (int i = 0; i < 4; i++) {
                const int r = m0 + i * 16 + g;
                af[i][0] = __float_as_uint(As[r * 20 + kb + c]);
                af[i][1] = __float_as_uint(As[(r + 8) * 20 + kb + c]);
                af[i][2] = __float_as_uint(As[r * 20 + kb + c + 4]);
                af[i][3] = __float_as_uint(As[(r + 8) * 20 + kb + c + 4]);
            }
#pragma unroll
            for (int j = 0; j < 4; j++) {
                const int col = n0 + j * 8 + g;
                bf[j][0] = __float_as_uint(Bs[(kb + c) * 136 + col]);
                bf[j][1] = __float_as_uint(Bs[(kb + c + 4) * 136 + col]);
            }
#pragma unroll
            for (int i = 0; i < 4; i++)
#pragma unroll
                for (int j = 0; j < 4; j++)
                    asm volatile(
                        "mma.sync.aligned.m16n8k8.row.col.f32.tf32.tf32.f32 "
                        "{%0,%1,%2,%3}, {%4,%5,%6,%7}, {%8,%9}, {%0,%1,%2,%3};\n"
                        : "+f"(acc[i][j][0]), "+f"(acc[i][j][1]),
                          "+f"(acc[i][j][2]), "+f"(acc[i][j][3])
                        : "r"(af[i][0]), "r"(af[i][1]), "r"(af[i][2]), "r"(af[i][3]),
                          "r"(bf[j][0]), "r"(bf[j][1]));
        }
    };

    // prologue: fill stages 0..S-2
#pragma unroll
    for (int s = 0; s < TG_STAGES - 1; s++) {
        if (s < nk) load_stage(s, s);
        cp_commit();
    }

    for (int kt = 0; kt < nk; ++kt) {
        cp_wait<TG_STAGES - 2>();
        __syncthreads();
        const int nxt = kt + TG_STAGES - 1;
        if (nxt < nk) load_stage(nxt, nxt & (TG_STAGES - 1));
        cp_commit();
        compute(kt & (TG_STAGES - 1));
    }

    // epilogue
#pragma unroll
    for (int i = 0; i < 4; i++) {
        const int r0 = bm + m0 + i * 16 + g;
#pragma unroll
        for (int j = 0; j < 4; j++) {
            const int col = bn + n0 + j * 8 + 2 * c;
            float v00 = acc[i][j][0], v01 = acc[i][j][1];
            float v10 = acc[i][j][2], v11 = acc[i][j][3];
            if (EPI == 1) {
                const float b0v = bias[col], b1v = bias[col + 1];
                v00 = softplusf_(v00 + b0v);
                v01 = softplusf_(v01 + b1v);
                v10 = softplusf_(v10 + b0v);
                v11 = softplusf_(v11 + b1v);
            }
            *(float2*)&C[(size_t)r0 * N + col]       = make_float2(v00, v01);
            *(float2*)&C[(size_t)(r0 + 8) * N + col] = make_float2(v10, v11);
        }
    }
}

// ============================================================================
// Depthwise causal conv (K=4) + bias + SiLU.
// ============================================================================
__global__ __launch_bounds__(256)
void conv_silu(const float* __restrict__ proj,
               const float* __restrict__ cw,
               const float* __restrict__ cb,
               float* __restrict__ h)
{
    int idx = blockIdx.x * blockDim.x + threadIdx.x;
    int d  = idx % DIn;
    int bt = idx / DIn;
    int t  = bt % Ln;

    float4 w = *(const float4*)(cw + d * 4);
    float acc = cb[d];
    const float* p = proj + (size_t)bt * (2 * DIn) + d;
    const int s = 2 * DIn;
    if (t >= 3) acc = fmaf(p[-3 * s], w.x, acc);
    if (t >= 2) acc = fmaf(p[-2 * s], w.y, acc);
    if (t >= 1) acc = fmaf(p[-1 * s], w.z, acc);
    acc = fmaf(p[0], w.w, acc);
    h[idx] = acc * sigmoidf_(acc);
}

// ============================================================================
// x_proj GEMM, split-K: ssm[4096,80] += h[4096,1536(chunk)] @ W[chunk,80].
// BM=64, 4 K-splits (384 each), grid (64,4), 256 thr (16x16, 4x5 per thread).
// Output accumulated with atomicAdd into zeroed g_ssm.
// ============================================================================
#define XKS 4
#define XKC (DIn / XKS)   /* 384 */
__global__ __launch_bounds__(256)
void gemm_xproj(const float* __restrict__ A,
                const float* __restrict__ W)
{
    __shared__ float As[2][16][68];   // [k][row], padded
    __shared__ float Ws[2][16][SP];

    const int tid = threadIdx.x;
    const int bm  = blockIdx.x << 6;
    const int k0  = blockIdx.y * XKC;
    const int tx  = tid & 15;
    const int ty  = tid >> 4;

    const int ar  = tid >> 2;           // 0..63
    const int ac4 = (tid & 3) << 2;     // 0,4,8,12

    float acc[4][5];
#pragma unroll
    for (int i = 0; i < 4; i++)
#pragma unroll
        for (int j = 0; j < 5; j++) acc[i][j] = 0.f;

    const float* Ap = A + (size_t)(bm + ar) * DIn + k0 + ac4;
    const int nk = XKC / 16;   // 24

    float4 aR; float wR[5];
    auto g2r = [&](int kt) {
        aR = *(const float4*)(Ap + kt * 16);
#pragma unroll
        for (int j = 0; j < 5; j++) {
            int e = tid + (j << 8);
            int k = e / SP, n2 = e % SP;
            wR[j] = W[(size_t)(k0 + kt * 16 + k) * SP + n2];
        }
    };
    auto r2s = [&](int buf) {
        As[buf][ac4 + 0][ar] = aR.x;
        As[buf][ac4 + 1][ar] = aR.y;
        As[buf][ac4 + 2][ar] = aR.z;
        As[buf][ac4 + 3][ar] = aR.w;
#pragma unroll
        for (int j = 0; j < 5; j++) {
            int e = tid + (j << 8);
            int k = e / SP, n2 = e % SP;
            Ws[buf][k][n2] = wR[j];
        }
    };

    g2r(0); r2s(0);
    __syncthreads();

    for (int kt = 0; kt < nk; ++kt) {
        const int buf = kt & 1;
        const bool more = (kt + 1 < nk);
        if (more) g2r(kt + 1);
#pragma unroll
        for (int k = 0; k < 16; k++) {
            float4 a4 = *(const float4*)&As[buf][k][ty << 2];
            float av[4] = {a4.x, a4.y, a4.z, a4.w};
#pragma unroll
            for (int j = 0; j < 5; j++) {
                float w = Ws[buf][k][tx * 5 + j];
#pragma unroll
                for (int i = 0; i < 4; i++)
                    acc[i][j] = fmaf(av[i], w, acc[i][j]);
            }
        }
        if (more) r2s(buf ^ 1);
        __syncthreads();
    }

#pragma unroll
    for (int i = 0; i < 4; i++) {
        const int row = bm + (ty << 2) + i;
#pragma unroll
        for (int j = 0; j < 5; j++)
            atomicAdd(&g_ssm[(size_t)row * SP + tx * 5 + j], acc[i][j]);
    }
}

// ============================================================================
// Fused selective scan + skip + gating (writes tf32-rounded y).
// ============================================================================
__global__ __launch_bounds__(128)
void scan_kernel(const float* __restrict__ Alog, const float* __restrict__ Dp)
{
    __shared__ float s_h [2][32][8];
    __shared__ float s_dt[2][32][8];
    __shared__ float s_g [2][32][8];
    __shared__ float s_B [2][32][16];
    __shared__ float s_C [2][32][16];

    const int tid  = threadIdx.x;
    const int lane = tid & 31;
    const int w    = tid >> 5;
    const int n    = lane & 15;
    const int half = lane >> 4;
    const int dl   = (w << 1) + half;
    const int blk  = blockIdx.x;
    const int b    = blk / (DIn / 8);
    const int d0   = (blk % (DIn / 8)) << 3;
    const int d    = d0 + dl;
    const int bL   = b * Ln;

    const float A_dn = -__expf(Alog[d * Nn + n]);
    const float Dv   = Dp[d];
    float state = 0.f;

    float rh[2], rdt[2], rg[2], rB[4], rC[4];

    auto do_load = [&](int c) {
        int t0 = c << 5;
#pragma unroll
        for (int j = 0; j < 2; j++) {
            int e = tid + (j << 7);
            int t = e >> 3, dd = e & 7;
            int row = bL + t0 + t;
            rh[j]  = g_h [(size_t)row * DIn + d0 + dd];
            rdt[j] = g_dt[(size_t)row * DIn + d0 + dd];
            rg[j]  = g_proj[(size_t)row * (2 * DIn) + DIn + d0 + dd];
        }
#pragma unroll
        for (int j = 0; j < 4; j++) {
            int e = tid + (j << 7);
            int t = e >> 4, nn = e & 15;
            int row = bL + t0 + t;
            rB[j] = g_ssm[(size_t)row * SP + Rn + nn];
            rC[j] = g_ssm[(size_t)row * SP + Rn + Nn + nn];
        }
    };
    auto do_store = [&](int buf) {
#pragma unroll
        for (int j = 0; j < 2; j++) {
            int e = tid + (j << 7);
            int t = e >> 3, dd = e & 7;
            s_h [buf][t][dd] = rh[j];
            s_dt[buf][t][dd] = rdt[j];
            s_g [buf][t][dd] = rg[j];
        }
#pragma unroll
        for (int j = 0; j < 4; j++) {
            int e = tid + (j << 7);
            int t = e >> 4, nn = e & 15;
            s_B[buf][t][nn] = rB[j];
            s_C[buf][t][nn] = rC[j];
        }
    };

    do_load(0);
    do_store(0);
    __syncthreads();

    const int NC = Ln / 32;
    for (int c = 0; c < NC; c++) {
        const int buf = c & 1;
        if (c + 1 < NC) do_load(c + 1);
        const int t0 = c << 5;
#pragma unroll 8
        for (int t = 0; t < 32; t++) {
            float dtv = s_dt[buf][t][dl];
            float hv  = s_h [buf][t][dl];
            float Bv  = s_B [buf][t][n];
            float Cv  = s_C [buf][t][n];
            float dA  = __expf(A_dn * dtv);
            state = fmaf(dA, state, Bv * hv);
            float p = state * Cv;
            p += __shfl_xor_sync(0xffffffffu, p, 8);
            p += __shfl_xor_sync(0xffffffffu, p, 4);
            p += __shfl_xor_sync(0xffffffffu, p, 2);
            p += __shfl_xor_sync(0xffffffffu, p, 1);
            if (n == 0) {
                float gv = s_g[buf][t][dl];
                float yv = (p + hv * Dv) * gv * sigmoidf_(gv);
                g_y[(size_t)(bL + t0 + t) * DIn + d] = roundtf(yv);
            }
        }
        if (c + 1 < NC) do_store(buf ^ 1);
        __syncthreads();
    }
}

// ============================================================================
extern "C" void kernel_launch(void* const* d_in, const int* in_sizes, int n_in,
                              void* d_out, int out_size)
{
    const float* x          = (const float*)d_in[0];
    const float* in_proj_w  = (const float*)d_in[1];
    const float* conv_w     = (const float*)d_in[2];
    const float* conv_b     = (const float*)d_in[3];
    const float* x_proj_w   = (const float*)d_in[4];
    const float* dt_proj_w  = (const float*)d_in[5];
    const float* dt_proj_b  = (const float*)d_in[6];
    const float* out_proj_w = (const float*)d_in[7];
    const float* A_log      = (const float*)d_in[8];
    const float* D_param    = (const float*)d_in[9];
    float* out = (float*)d_out;

    float *proj, *h, *dtraw, *dt, *y, *xr, *w1, *w2, *w3;
    cudaGetSymbolAddress((void**)&proj,  g_proj);
    cudaGetSymbolAddress((void**)&h,     g_h);
    cudaGetSymbolAddress((void**)&dtraw, g_dtraw);
    cudaGetSymbolAddress((void**)&dt,    g_dt);
    cudaGetSymbolAddress((void**)&y,     g_y);
    cudaGetSymbolAddress((void**)&xr,    g_xr);
    cudaGetSymbolAddress((void**)&w1,    g_w1);
    cudaGetSymbolAddress((void**)&w2,    g_w2);
    cudaGetSymbolAddress((void**)&w3,    g_w3);

    static bool attr_done = false;
    if (!attr_done) {
        cudaFuncSetAttribute(tgemm<0>, cudaFuncAttributeMaxDynamicSharedMemorySize, TG_SMEM);
        cudaFuncSetAttribute(tgemm<1>, cudaFuncAttributeMaxDynamicSharedMemorySize, TG_SMEM);
        attr_done = true;
    }

    // 0) pre-round x + weights; zero split-K accumulator
    size_t tot4 = (S0 + S1 + S2 + S3) / 4;
    preround<<<(unsigned)((tot4 + 255) / 256), 256>>>(x, in_proj_w, dt_proj_w, out_proj_w);
    zero_ssm<<<(BLn * SP / 4 + 255) / 256, 256>>>();

    // 1) proj = x @ in_proj_w   [4096,3072], K=768
    tgemm<0><<<dim3((2 * DIn) / 128, BLn / 128), 256, TG_SMEM>>>(
        xr, Hn, w1, proj, 2 * DIn, Hn, nullptr);

    // 2) depthwise causal conv + SiLU -> g_h
    conv_silu<<<(BLn * DIn) / 256, 256>>>(proj, conv_w, conv_b, h);

    // 3) ssm += h @ x_proj_w   [4096,80] split-K
    gemm_xproj<<<dim3(BLn / 64, XKS), 256>>>(h, x_proj_w);
    round_dtraw<<<(BLn * Rn + 255) / 256, 256>>>();

    // 4) dt = softplus(dt_raw @ dt_proj_w + b)   [4096,1536], K=48
    tgemm<1><<<dim3(DIn / 128, BLn / 128), 256, TG_SMEM>>>(
        dtraw, Rn, w2, dt, DIn, Rn, dt_proj_b);

    // 5) selective scan (+ skip + gating)
    scan_kernel<<<Bn * (DIn / 8), 128>>>(A_log, D_param);

    // 6) out = y @ out_proj_w   [4096,768], K=1536
    tgemm<0><<<dim3(Hn / 128, BLn / 128), 256, TG_SMEM>>>(
        y, DIn, w3, out, Hn, DIn, nullptr);
}

// round 7
// speedup vs baseline: 1.2849x; 1.2318x over previous
#include <cuda_runtime.h>
#include <cstdint>
#include <cstddef>

#define Bn   2
#define Ln   2048
#define Hn   768
#define DIn  1536
#define Nn   16
#define Rn   48
#define BLn  (Bn*Ln)     /* 4096 */
#define SP   (Rn + 2*Nn) /* 80 */

// -------- scratch (static device globals; no allocation allowed) --------
__device__ float g_proj [(size_t)BLn * 2 * DIn];  // in_proj output (h | gate)
__device__ float g_h    [(size_t)BLn * DIn];      // conv+silu output
__device__ float g_ssm  [(size_t)BLn * SP];       // x_proj output (dt_raw|B|C)
__device__ float g_dtraw[(size_t)BLn * Rn];       // tf32-rounded dt_raw copy
__device__ float g_dt   [(size_t)BLn * DIn];      // softplus(dt)
__device__ float g_y    [(size_t)BLn * DIn];      // scan output (tf32-rounded)
__device__ float g_xr   [(size_t)BLn * Hn];       // tf32-rounded x
__device__ float g_w1   [(size_t)Hn * 2 * DIn];   // in_proj_w^T  [3072][768], tf32
__device__ float g_w2   [(size_t)Rn * DIn];       // dt_proj_w^T  [1536][48],  tf32
__device__ float g_w3   [(size_t)DIn * Hn];       // out_proj_w^T [768][1536], tf32

__device__ __forceinline__ float sigmoidf_(float x) { return 1.f / (1.f + __expf(-x)); }
__device__ __forceinline__ uint32_t f2tf(float f) {
    uint32_t u; asm("cvt.rna.tf32.f32 %0, %1;" : "=r"(u) : "f"(f)); return u;
}
__device__ __forceinline__ float roundtf(float f) { return __uint_as_float(f2tf(f)); }
__device__ __forceinline__ float softplusf_(float x) {
    return fmaxf(x, 0.f) + log1pf(__expf(-fabsf(x)));
}
__device__ __forceinline__ void cp16s(uint32_t sa, const void* g) {
    asm volatile("cp.async.cg.shared.global [%0], [%1], 16;\n" :: "r"(sa), "l"(g));
}
__device__ __forceinline__ void cp_commit() {
    asm volatile("cp.async.commit_group;\n");
}
template<int NN>
__device__ __forceinline__ void cp_wait() {
    asm volatile("cp.async.wait_group %0;\n" :: "n"(NN));
}
__device__ __forceinline__ uint32_t smem_u32(const void* p) {
    return (uint32_t)__cvta_generic_to_shared(p);
}
__device__ __forceinline__ void ldsm_x4(uint32_t& r0, uint32_t& r1, uint32_t& r2,
                                        uint32_t& r3, uint32_t a) {
    asm volatile("ldmatrix.sync.aligned.m8n8.x4.shared.b16 {%0,%1,%2,%3}, [%4];"
                 : "=r"(r0), "=r"(r1), "=r"(r2), "=r"(r3) : "r"(a));
}
__device__ __forceinline__ void ldsm_x2(uint32_t& r0, uint32_t& r1, uint32_t a) {
    asm volatile("ldmatrix.sync.aligned.m8n8.x2.shared.b16 {%0,%1}, [%2];"
                 : "=r"(r0), "=r"(r1) : "r"(a));
}

// ============================================================================
// preround: tf32-round x (float4 grid-stride).
// ============================================================================
#define S0 ((size_t)BLn * Hn)
__global__ __launch_bounds__(256)
void preround(const float* __restrict__ x)
{
    size_t i = ((size_t)blockIdx.x * blockDim.x + threadIdx.x) * 4;
    if (i >= S0) return;
    float4 v = *(const float4*)(x + i);
    v.x = roundtf(v.x); v.y = roundtf(v.y); v.z = roundtf(v.z); v.w = roundtf(v.w);
    *(float4*)(g_xr + i) = v;
}

// dst[c][r] = round_tf32(src[r][c]); src [R][C] -> dst [C][R]. Bounds-guarded.
__global__ __launch_bounds__(256)
void transpose_round(const float* __restrict__ src, float* __restrict__ dst,
                     int R, int C)
{
    __shared__ float t[32][33];
    const int bx = blockIdx.x << 5;
    const int by = blockIdx.y << 5;
    const int tx = threadIdx.x & 31;
    const int ty = threadIdx.x >> 5;
#pragma unroll
    for (int i = 0; i < 32; i += 8) {
        int r = by + ty + i, c = bx + tx;
        if (r < R && c < C) t[ty + i][tx] = src[(size_t)r * C + c];
    }
    __syncthreads();
#pragma unroll
    for (int i = 0; i < 32; i += 8) {
        int r = bx + ty + i, c = by + tx;
        // dst[r][c] = src[c][r] = t[tx][ty+i]  (FIXED: was t[ty+i][tx])
        if (r < C && c < R) dst[(size_t)r * R + c] = roundtf(t[tx][ty + i]);
    }
}

__global__ __launch_bounds__(256)
void zero_ssm()
{
    size_t i = ((size_t)blockIdx.x * blockDim.x + threadIdx.x) * 4;
    if (i < (size_t)BLn * SP) *(float4*)&g_ssm[i] = make_float4(0.f, 0.f, 0.f, 0.f);
}

__global__ __launch_bounds__(256)
void round_dtraw()
{
    int i = blockIdx.x * blockDim.x + threadIdx.x;
    if (i >= BLn * Rn) return;
    int row = i / Rn, col = i - row * Rn;
    g_dtraw[i] = roundtf(g_ssm[(size_t)row * SP + col]);
}

// ============================================================================
// TF32 mma.sync GEMM with ldmatrix fragments, 4-stage cp.async.
// C[M,N] = A[M,K](lda) @ Bt[N,K](ldb)^T.   A,Bt pre-rounded tf32.
// Tile 128x128x16, 8 warps of 64x32. EPI==1: C = softplus(C + bias[n]).
// smem per stage: A[128][20] + Bt[128][20] floats.
// ============================================================================
#define TG_STAGES 4
#define TG_TSZ (128 * 20)                  /* floats per operand tile */
#define TG_STG (2 * TG_TSZ)                /* floats per stage */
#define TG_SMEM (TG_STAGES * TG_STG * 4)   /* 81920 bytes */

template<int EPI>
__global__ __launch_bounds__(256, 2)
void tgemm(const float* __restrict__ A, int lda,
           const float* __restrict__ Bt, int ldb,
           float* __restrict__ C, int N, int K,
           const float* __restrict__ bias)
{
    extern __shared__ float smem[];

    const int tid  = threadIdx.x;
    const int lane = tid & 31;
    const int warp = tid >> 5;
    const int wm   = warp >> 2;        // 0..1
    const int wn   = warp & 3;         // 0..3
    const int m0   = wm * 64;
    const int n0   = wn * 32;
    const int g    = lane >> 2;
    const int c    = lane & 3;

    const int bm = blockIdx.y << 7;
    const int bn = blockIdx.x << 7;

    // cp.async mapping: 512 chunks of 16B per operand tile; 2 per thread.
    const int ch0 = tid * 2;
    const uint32_t smem0 = smem_u32(smem);

    const int r0a = ch0 >> 2,       k0a = (ch0 & 3) << 2;
    const int r1a = (ch0 + 1) >> 2, k1a = ((ch0 + 1) & 3) << 2;
    const float* Ap0 = A  + (size_t)(bm + r0a) * lda + k0a;
    const float* Ap1 = A  + (size_t)(bm + r1a) * lda + k1a;
    const float* Bp0 = Bt + (size_t)(bn + r0a) * ldb + k0a;
    const float* Bp1 = Bt + (size_t)(bn + r1a) * ldb + k1a;
    const uint32_t sA0 = (uint32_t)(r0a * 20 + k0a) * 4;
    const uint32_t sA1 = (uint32_t)(r1a * 20 + k1a) * 4;

    // ldmatrix per-lane base addresses
    const int arow = m0 + (lane & 7) + ((lane & 8) ? 8 : 0);
    const int acol = (lane & 16) ? 4 : 0;
    const uint32_t aBase = (uint32_t)(arow * 20 + acol) * 4;
    const int brow = n0 + (lane & 7);
    const int bcol = (lane & 8) ? 4 : 0;
    const uint32_t bBase = (uint32_t)(brow * 20 + bcol) * 4;

    float acc[4][4][4];
#pragma unroll
    for (int i = 0; i < 4; i++)
#pragma unroll
        for (int j = 0; j < 4; j++)
#pragma unroll
            for (int q = 0; q < 4; q++) acc[i][j][q] = 0.f;

    const int nk = K >> 4;

    auto load_stage = [&](int kt, int s) {
        const uint32_t st = smem0 + (uint32_t)(s * TG_STG) * 4;
        const int k0 = kt << 4;
        cp16s(st + sA0,               Ap0 + k0);
        cp16s(st + sA1,               Ap1 + k0);
        cp16s(st + TG_TSZ * 4 + sA0,  Bp0 + k0);
        cp16s(st + TG_TSZ * 4 + sA1,  Bp1 + k0);
    };
    auto compute = [&](int s) {
        const uint32_t stA = smem0 + (uint32_t)(s * TG_STG) * 4;
        const uint32_t stB = stA + TG_TSZ * 4;
#pragma unroll
        for (int ks = 0; ks < 2; ks++) {
            const uint32_t kb = (ks << 3) * 4;
            uint32_t af[4][4], bf[4][2];
#pragma unroll
            for (int i = 0; i < 4; i++)
                ldsm_x4(af[i][0], af[i][1], af[i][2], af[i][3],
                        stA + aBase + (uint32_t)(i * 16 * 20) * 4 + kb);
#pragma unroll
            for (int j = 0; j < 4; j++)
                ldsm_x2(bf[j][0], bf[j][1],
                        stB + bBase + (uint32_t)(j * 8 * 20) * 4 + kb);
#pragma unroll
            for (int i = 0; i < 4; i++)
#pragma unroll
                for (int j = 0; j < 4; j++)
                    asm volatile(
                        "mma.sync.aligned.m16n8k8.row.col.f32.tf32.tf32.f32 "
                        "{%0,%1,%2,%3}, {%4,%5,%6,%7}, {%8,%9}, {%0,%1,%2,%3};\n"
                        : "+f"(acc[i][j][0]), "+f"(acc[i][j][1]),
                          "+f"(acc[i][j][2]), "+f"(acc[i][j][3])
                        : "r"(af[i][0]), "r"(af[i][1]), "r"(af[i][2]), "r"(af[i][3]),
                          "r"(bf[j][0]), "r"(bf[j][1]));
        }
    };

#pragma unroll
    for (int s = 0; s < TG_STAGES - 1; s++) {
        if (s < nk) load_stage(s, s);
        cp_commit();
    }
    for (int kt = 0; kt < nk; ++kt) {
        cp_wait<TG_STAGES - 2>();
        __syncthreads();
        const int nxt = kt + TG_STAGES - 1;
        if (nxt < nk) load_stage(nxt, nxt & (TG_STAGES - 1));
        cp_commit();
        compute(kt & (TG_STAGES - 1));
    }

    // epilogue
#pragma unroll
    for (int i = 0; i < 4; i++) {
        const int r0 = bm + m0 + i * 16 + g;
#pragma unroll
        for (int j = 0; j < 4; j++) {
            const int col = bn + n0 + j * 8 + 2 * c;
            float v00 = acc[i][j][0], v01 = acc[i][j][1];
            float v10 = acc[i][j][2], v11 = acc[i][j][3];
            if (EPI == 1) {
                const float b0v = bias[col], b1v = bias[col + 1];
                v00 = softplusf_(v00 + b0v);
                v01 = softplusf_(v01 + b1v);
                v10 = softplusf_(v10 + b0v);
                v11 = softplusf_(v11 + b1v);
            }
            *(float2*)&C[(size_t)r0 * N + col]       = make_float2(v00, v01);
            *(float2*)&C[(size_t)(r0 + 8) * N + col] = make_float2(v10, v11);
        }
    }
}

// ============================================================================
// Depthwise causal conv (K=4) + bias + SiLU, 4 channels/thread.
// ============================================================================
__global__ __launch_bounds__(256)
void conv_silu(const float* __restrict__ proj,
               const float* __restrict__ cw,
               const float* __restrict__ cb,
               float* __restrict__ h)
{
    int idx = blockIdx.x * blockDim.x + threadIdx.x;   // over BLn*DIn/4
    int d4 = (idx % (DIn / 4)) << 2;
    int bt = idx / (DIn / 4);
    int t  = bt % Ln;

    const float* p = proj + (size_t)bt * (2 * DIn) + d4;
    const int s = 2 * DIn;
    float4 z  = make_float4(0.f, 0.f, 0.f, 0.f);
    float4 x0 = *(const float4*)p;
    float4 x1 = (t >= 1) ? *(const float4*)(p - s)     : z;
    float4 x2 = (t >= 2) ? *(const float4*)(p - 2 * s) : z;
    float4 x3 = (t >= 3) ? *(const float4*)(p - 3 * s) : z;
    float4 cbv = *(const float4*)(cb + d4);
    float4 w0 = *(const float4*)(cw + (d4 + 0) * 4);
    float4 w1 = *(const float4*)(cw + (d4 + 1) * 4);
    float4 w2 = *(const float4*)(cw + (d4 + 2) * 4);
    float4 w3 = *(const float4*)(cw + (d4 + 3) * 4);

    float4 o;
    o.x = fmaf(x3.x, w0.x, fmaf(x2.x, w0.y, fmaf(x1.x, w0.z, fmaf(x0.x, w0.w, cbv.x))));
    o.y = fmaf(x3.y, w1.x, fmaf(x2.y, w1.y, fmaf(x1.y, w1.z, fmaf(x0.y, w1.w, cbv.y))));
    o.z = fmaf(x3.z, w2.x, fmaf(x2.z, w2.y, fmaf(x1.z, w2.z, fmaf(x0.z, w2.w, cbv.z))));
    o.w = fmaf(x3.w, w3.x, fmaf(x2.w, w3.y, fmaf(x1.w, w3.z, fmaf(x0.w, w3.w, cbv.w))));
    o.x = o.x * sigmoidf_(o.x);
    o.y = o.y * sigmoidf_(o.y);
    o.z = o.z * sigmoidf_(o.z);
    o.w = o.w * sigmoidf_(o.w);
    *(float4*)(h + (size_t)bt * DIn + d4) = o;
}

// ============================================================================
// x_proj GEMM, split-K: ssm += h @ x_proj_w.
// ============================================================================
#define XKS 4
#define XKC (DIn / XKS)
__global__ __launch_bounds__(256)
void gemm_xproj(const float* __restrict__ A,
                const float* __restrict__ W)
{
    __shared__ float As[2][16][68];
    __shared__ float Ws[2][16][SP];

    const int tid = threadIdx.x;
    const int bm  = blockIdx.x << 6;
    const int k0  = blockIdx.y * XKC;
    const int tx  = tid & 15;
    const int ty  = tid >> 4;
    const int ar  = tid >> 2;
    const int ac4 = (tid & 3) << 2;

    float acc[4][5];
#pragma unroll
    for (int i = 0; i < 4; i++)
#pragma unroll
        for (int j = 0; j < 5; j++) acc[i][j] = 0.f;

    const float* Ap = A + (size_t)(bm + ar) * DIn + k0 + ac4;
    const int nk = XKC / 16;

    float4 aR; float wR[5];
    auto g2r = [&](int kt) {
        aR = *(const float4*)(Ap + kt * 16);
#pragma unroll
        for (int j = 0; j < 5; j++) {
            int e = tid + (j << 8);
            int k = e / SP, n2 = e % SP;
            wR[j] = W[(size_t)(k0 + kt * 16 + k) * SP + n2];
        }
    };
    auto r2s = [&](int buf) {
        As[buf][ac4 + 0][ar] = aR.x;
        As[buf][ac4 + 1][ar] = aR.y;
        As[buf][ac4 + 2][ar] = aR.z;
        As[buf][ac4 + 3][ar] = aR.w;
#pragma unroll
        for (int j = 0; j < 5; j++) {
            int e = tid + (j << 8);
            int k = e / SP, n2 = e % SP;
            Ws[buf][k][n2] = wR[j];
        }
    };

    g2r(0); r2s(0);
    __syncthreads();

    for (int kt = 0; kt < nk; ++kt) {
        const int buf = kt & 1;
        const bool more = (kt + 1 < nk);
        if (more) g2r(kt + 1);
#pragma unroll
        for (int k = 0; k < 16; k++) {
            float4 a4 = *(const float4*)&As[buf][k][ty << 2];
            float av[4] = {a4.x, a4.y, a4.z, a4.w};
#pragma unroll
            for (int j = 0; j < 5; j++) {
                float w = Ws[buf][k][tx * 5 + j];
#pragma unroll
                for (int i = 0; i < 4; i++)
                    acc[i][j] = fmaf(av[i], w, acc[i][j]);
            }
        }
        if (more) r2s(buf ^ 1);
        __syncthreads();
    }

#pragma unroll
    for (int i = 0; i < 4; i++) {
        const int row = bm + (ty << 2) + i;
#pragma unroll
        for (int j = 0; j < 5; j++)
            atomicAdd(&g_ssm[(size_t)row * SP + tx * 5 + j], acc[i][j]);
    }
}

// ============================================================================
// Fused selective scan + skip + gating. 8-timestep batched shuffle reduction.
// ============================================================================
__global__ __launch_bounds__(128)
void scan_kernel(const float* __restrict__ Alog, const float* __restrict__ Dp)
{
    __shared__ float s_h [2][32][8];
    __shared__ float s_dt[2][32][8];
    __shared__ float s_g [2][32][8];
    __shared__ float s_B [2][32][16];
    __shared__ float s_C [2][32][16];

    const int tid  = threadIdx.x;
    const int lane = tid & 31;
    const int w    = tid >> 5;
    const int n    = lane & 15;
    const int half = lane >> 4;
    const int dl   = (w << 1) + half;
    const int blk  = blockIdx.x;
    const int b    = blk / (DIn / 8);
    const int d0   = (blk % (DIn / 8)) << 3;
    const int d    = d0 + dl;
    const int bL   = b * Ln;

    const float A_dn = -__expf(Alog[d * Nn + n]);
    const float Dv   = Dp[d];
    float state = 0.f;

    float rh[2], rdt[2], rg[2], rB[4], rC[4];

    auto do_load = [&](int c) {
        int t0 = c << 5;
#pragma unroll
        for (int j = 0; j < 2; j++) {
            int e = tid + (j << 7);
            int t = e >> 3, dd = e & 7;
            int row = bL + t0 + t;
            rh[j]  = g_h [(size_t)row * DIn + d0 + dd];
            rdt[j] = g_dt[(size_t)row * DIn + d0 + dd];
            rg[j]  = g_proj[(size_t)row * (2 * DIn) + DIn + d0 + dd];
        }
#pragma unroll
        for (int j = 0; j < 4; j++) {
            int e = tid + (j << 7);
            int t = e >> 4, nn = e & 15;
            int row = bL + t0 + t;
            rB[j] = g_ssm[(size_t)row * SP + Rn + nn];
            rC[j] = g_ssm[(size_t)row * SP + Rn + Nn + nn];
        }
    };
    auto do_store = [&](int buf) {
#pragma unroll
        for (int j = 0; j < 2; j++) {
            int e = tid + (j << 7);
            int t = e >> 3, dd = e & 7;
            s_h [buf][t][dd] = rh[j];
            s_dt[buf][t][dd] = rdt[j];
            s_g [buf][t][dd] = rg[j];
        }
#pragma unroll
        for (int j = 0; j < 4; j++) {
            int e = tid + (j << 7);
            int t = e >> 4, nn = e & 15;
            s_B[buf][t][nn] = rB[j];
            s_C[buf][t][nn] = rC[j];
        }
    };

    do_load(0);
    do_store(0);
    __syncthreads();

    const int NC = Ln / 32;
    for (int c = 0; c < NC; c++) {
        const int buf = c & 1;
        if (c + 1 < NC) do_load(c + 1);
        const int t0 = c << 5;
#pragma unroll
        for (int tb = 0; tb < 32; tb += 8) {
            float p[8], hs[8];
#pragma unroll
            for (int tt = 0; tt < 8; tt++) {
                const int t = tb + tt;
                float dtv = s_dt[buf][t][dl];
                float hv  = s_h [buf][t][dl];
                float Bv  = s_B [buf][t][n];
                float Cv  = s_C [buf][t][n];
                float dA  = __expf(A_dn * dtv);
                state = fmaf(dA, state, Bv * hv);
                p[tt]  = state * Cv;
                hs[tt] = hv;
            }
            // 16-lane reductions, 8 independent chains
#pragma unroll
            for (int st = 8; st >= 1; st >>= 1)
#pragma unroll
                for (int tt = 0; tt < 8; tt++)
                    p[tt] += __shfl_xor_sync(0xffffffffu, p[tt], st);
            if (n == 0) {
#pragma unroll
                for (int tt = 0; tt < 8; tt++) {
                    const int t = tb + tt;
                    float gv = s_g[buf][t][dl];
                    float yv = (p[tt] + hs[tt] * Dv) * gv * sigmoidf_(gv);
                    g_y[(size_t)(bL + t0 + t) * DIn + d] = roundtf(yv);
                }
            }
        }
        if (c + 1 < NC) do_store(buf ^ 1);
        __syncthreads();
    }
}

// ============================================================================
extern "C" void kernel_launch(void* const* d_in, const int* in_sizes, int n_in,
                              void* d_out, int out_size)
{
    const float* x          = (const float*)d_in[0];
    const float* in_proj_w  = (const float*)d_in[1];
    const float* conv_w     = (const float*)d_in[2];
    const float* conv_b     = (const float*)d_in[3];
    const float* x_proj_w   = (const float*)d_in[4];
    const float* dt_proj_w  = (const float*)d_in[5];
    const float* dt_proj_b  = (const float*)d_in[6];
    const float* out_proj_w = (const float*)d_in[7];
    const float* A_log      = (const float*)d_in[8];
    const float* D_param    = (const float*)d_in[9];
    float* out = (float*)d_out;

    float *proj, *h, *dtraw, *dt, *y, *xr, *w1t, *w2t, *w3t;
    cudaGetSymbolAddress((void**)&proj,  g_proj);
    cudaGetSymbolAddress((void**)&h,     g_h);
    cudaGetSymbolAddress((void**)&dtraw, g_dtraw);
    cudaGetSymbolAddress((void**)&dt,    g_dt);
    cudaGetSymbolAddress((void**)&y,     g_y);
    cudaGetSymbolAddress((void**)&xr,    g_xr);
    cudaGetSymbolAddress((void**)&w1t,   g_w1);
    cudaGetSymbolAddress((void**)&w2t,   g_w2);
    cudaGetSymbolAddress((void**)&w3t,   g_w3);

    cudaFuncSetAttribute(tgemm<0>, cudaFuncAttributeMaxDynamicSharedMemorySize, TG_SMEM);
    cudaFuncSetAttribute(tgemm<1>, cudaFuncAttributeMaxDynamicSharedMemorySize, TG_SMEM);

    // 0) pre-round x; transpose+round w1, w2, w3; zero split-K accumulator
    preround<<<(unsigned)((S0 / 4 + 255) / 256), 256>>>(x);
    transpose_round<<<dim3((2 * DIn) / 32, Hn / 32), 256>>>(in_proj_w,  w1t, Hn, 2 * DIn);
    transpose_round<<<dim3(DIn / 32, (Rn + 31) / 32), 256>>>(dt_proj_w, w2t, Rn, DIn);
    transpose_round<<<dim3(Hn / 32, DIn / 32), 256>>>(out_proj_w, w3t, DIn, Hn);
    zero_ssm<<<(BLn * SP / 4 + 255) / 256, 256>>>();

    // 1) proj = x @ in_proj_w   [4096,3072], K=768
    tgemm<0><<<dim3((2 * DIn) / 128, BLn / 128), 256, TG_SMEM>>>(
        xr, Hn, w1t, Hn, proj, 2 * DIn, Hn, nullptr);

    // 2) depthwise causal conv + SiLU -> g_h
    conv_silu<<<(BLn * DIn / 4) / 256, 256>>>(proj, conv_w, conv_b, h);

    // 3) ssm += h @ x_proj_w   [4096,80] split-K
    gemm_xproj<<<dim3(BLn / 64, XKS), 256>>>(h, x_proj_w);
    round_dtraw<<<(BLn * Rn + 255) / 256, 256>>>();

    // 4) dt = softplus(dt_raw @ dt_proj_w + b)   [4096,1536], K=48
    tgemm<1><<<dim3(DIn / 128, BLn / 128), 256, TG_SMEM>>>(
        dtraw, Rn, w2t, Rn, dt, DIn, Rn, dt_proj_b);

    // 5) selective scan (+ skip + gating)
    scan_kernel<<<Bn * (DIn / 8), 128>>>(A_log, D_param);

    // 6) out = y @ out_proj_w   [4096,768], K=1536
    tgemm<0><<<dim3(Hn / 128, BLn / 128), 256, TG_SMEM>>>(
        y, DIn, w3t, DIn, out, Hn, DIn, nullptr);
}